// round 13
// baseline (speedup 1.0000x reference)
#include <cuda_runtime.h>
#include <math.h>

#define Bq 8
#define Sq 1024
#define Dq 1024
#define Fq 3584
#define Eq 2
#define EPSq 1e-6f

typedef unsigned long long ull;

// ---------------- device scratch (no allocation) ----------------
__device__ float g_h1t[Dq * Bq];            // h1 transposed [d][b]
__device__ ull   g_pvu[64 * 4 * Dq];        // v0 partials [ic*4+p][j] (b-pairs)
__device__ float g_attn[Bq * Dq];           // attn output (atomic)
__device__ float g_h2t[Dq * Bq];            // h2 transposed [d][b]
__device__ float g_accg[Eq * Bq * Fq];      // gate acc (atomic)
__device__ float g_accu[Eq * Bq * Fq];      // up acc (atomic)
__device__ float g_y[Bq * Dq];              // moe output (atomic)
__device__ int   g_selG[Bq];                // router selection
__device__ float g_twG[Bq];                 // router top weight

// ---------------- f32x2 helpers ----------------
__device__ __forceinline__ ull pack2(float lo, float hi) {
    ull r;
    asm("mov.b64 %0, {%1, %2};" : "=l"(r) : "r"(__float_as_uint(lo)), "r"(__float_as_uint(hi)));
    return r;
}
__device__ __forceinline__ void unpack2(ull v, float& lo, float& hi) {
    unsigned a, b;
    asm("mov.b64 {%0, %1}, %2;" : "=r"(a), "=r"(b) : "l"(v));
    lo = __uint_as_float(a); hi = __uint_as_float(b);
}
#define FMA2(d, a, b) asm("fma.rn.f32x2 %0, %1, %2, %0;" : "+l"(d) : "l"(a), "l"(b))
#define ADD2(d, a)    asm("add.rn.f32x2 %0, %0, %1;"     : "+l"(d) : "l"(a))

// ---------------- multi-value block reduction ----------
template <int NV, int NWP>
__device__ __forceinline__ void breduce(const float* v, float* s_red, float* s_out) {
    int lane = threadIdx.x & 31, w = threadIdx.x >> 5;
#pragma unroll
    for (int k = 0; k < NV; k++) {
        float x = v[k];
#pragma unroll
        for (int o = 16; o; o >>= 1) x += __shfl_xor_sync(0xffffffffu, x, o);
        if (lane == 0) s_red[k * NWP + w] = x;
    }
    __syncthreads();
    if (threadIdx.x < NV) {
        float s = 0.f;
#pragma unroll
        for (int j = 0; j < NWP; j++) s += s_red[threadIdx.x * NWP + j];
        s_out[threadIdx.x] = s;
    }
    __syncthreads();
}

// ============ K0: zero accs + h1 = rmsnorm(x0)*ln1_w -> g_h1t. 8 blocks ============
__global__ void __launch_bounds__(256) k0_prep(
    const float* __restrict__ hidden, const float* __restrict__ ln1w)
{
    __shared__ float s_red[1 * 8];
    __shared__ float s_out[1];
    __shared__ float s_rs[1];
    const int tid = threadIdx.x, b = blockIdx.x;

    // zero atomic accumulators (spread across 8 blocks)
    for (int idx = b * 256 + tid; idx < Eq * Bq * Fq; idx += 8 * 256) {
        g_accg[idx] = 0.f; g_accu[idx] = 0.f;
    }
    for (int idx = b * 256 + tid; idx < Bq * Dq; idx += 8 * 256) {
        g_attn[idx] = 0.f; g_y[idx] = 0.f;
    }

    float xv[4];
    float ss[1]; ss[0] = 0.f;
#pragma unroll
    for (int it = 0; it < 4; it++) {
        int d = tid + it * 256;
        xv[it] = hidden[(size_t)b * Sq * Dq + d];
        ss[0] += xv[it] * xv[it];
    }
    breduce<1, 8>(ss, s_red, s_out);
    if (tid == 0) s_rs[0] = rsqrtf(s_out[0] * (1.f / Dq) + EPSq);
    __syncthreads();
    float rs = s_rs[0];
#pragma unroll
    for (int it = 0; it < 4; it++) {
        int d = tid + it * 256;
        g_h1t[d * Bq + b] = xv[it] * rs * ln1w[d];
    }
}

// ============ K1: v0 partials (pure matvec). 256 blocks: 64 ic(16) x 4 jc ============
__global__ void __launch_bounds__(256) k1_v(const float* __restrict__ vw)
{
    __shared__ float s_h[16 * Bq];
    const int tid = threadIdx.x, blk = blockIdx.x;
    ull* s_hu = (ull*)s_h;
    const int ic = blk >> 2, jc = blk & 3;
    const int ib = ic * 16;
    if (tid < 32) ((float4*)s_h)[tid] = ((const float4*)(g_h1t + ib * Bq))[tid];
    __syncthreads();
    int j = jc * 256 + tid;
    float w[16];
#pragma unroll
    for (int u = 0; u < 16; u++) w[u] = vw[(size_t)(ib + u) * Dq + j];
    ull acc[4] = {0, 0, 0, 0};
#pragma unroll
    for (int u = 0; u < 16; u++) {
        ull w2 = pack2(w[u], w[u]);
#pragma unroll
        for (int p = 0; p < 4; p++) FMA2(acc[p], s_hu[u * 4 + p], w2);
    }
#pragma unroll
    for (int p = 0; p < 4; p++) g_pvu[(size_t)(ic * 4 + p) * Dq + j] = acc[p];
}

// ============ K2: attn = v0 @ o_w ============
__global__ void __launch_bounds__(256) k2_o(const float* __restrict__ ow)
{
    __shared__ float s_v[16 * Bq];
    const int tid = threadIdx.x, blk = blockIdx.x;
    ull* s_vu = (ull*)s_v;
    int ic = blk >> 2, jc = blk & 3;
    int ib = ic * 16;
    if (tid < 64) {
        int i = tid >> 2, p = tid & 3;
        ull s = 0;
#pragma unroll 8
        for (int c = 0; c < 64; c++) {
            ull v = g_pvu[(size_t)(c * 4 + p) * Dq + ib + i];
            ADD2(s, v);
        }
        s_vu[i * 4 + p] = s;
    }
    __syncthreads();
    int j = jc * 256 + tid;
    float w[16];
#pragma unroll
    for (int u = 0; u < 16; u++) w[u] = ow[(size_t)(ib + u) * Dq + j];
    ull acc[4] = {0, 0, 0, 0};
#pragma unroll
    for (int u = 0; u < 16; u++) {
        ull w2 = pack2(w[u], w[u]);
#pragma unroll
        for (int p = 0; p < 4; p++) FMA2(acc[p], s_vu[u * 4 + p], w2);
    }
#pragma unroll
    for (int p = 0; p < 4; p++) {
        float lo, hi; unpack2(acc[p], lo, hi);
        atomicAdd(&g_attn[(2 * p) * Dq + j], lo);
        atomicAdd(&g_attn[(2 * p + 1) * Dq + j], hi);
    }
}

// ============ K2b: xmid -> h2 (global, transposed) + router. 8 blocks ============
__global__ void __launch_bounds__(256) k2b_h2(
    const float* __restrict__ hidden, const float* __restrict__ ln2w,
    const float* __restrict__ rw)
{
    __shared__ float s_red[2 * 8];
    __shared__ float s_out[2];
    __shared__ float s_rs[1];
    const int tid = threadIdx.x, b = blockIdx.x;
    float xm[4];
    float ss[1]; ss[0] = 0.f;
#pragma unroll
    for (int it = 0; it < 4; it++) {
        int d = tid + it * 256;
        xm[it] = hidden[(size_t)b * Sq * Dq + d] + g_attn[b * Dq + d];
        ss[0] += xm[it] * xm[it];
    }
    breduce<1, 8>(ss, s_red, s_out);
    if (tid == 0) s_rs[0] = rsqrtf(s_out[0] * (1.f / Dq) + EPSq);
    __syncthreads();
    float rs = s_rs[0];
    float l[2]; l[0] = 0.f; l[1] = 0.f;
#pragma unroll
    for (int it = 0; it < 4; it++) {
        int d = tid + it * 256;
        float h2 = xm[it] * rs * ln2w[d];
        g_h2t[d * Bq + b] = h2;
        l[0] = fmaf(h2, rw[d * 2 + 0], l[0]);
        l[1] = fmaf(h2, rw[d * 2 + 1], l[1]);
    }
    breduce<2, 8>(l, s_red, s_out);
    if (tid == 0) {
        float l0 = s_out[0], l1 = s_out[1];
        g_selG[b] = (l1 > l0) ? 1 : 0;
        g_twG[b]  = 1.f / (1.f + expf(-fabsf(l0 - l1)));
    }
}

// ============ K3: gate|up matvec, float2 + double-buffered. 448 blocks ============
__global__ void __launch_bounds__(256, 3) k3_gateup(
    const float* __restrict__ gw, const float* __restrict__ uw)
{
    __shared__ float s_h[128 * Bq];        // local h2 slice [il][b] (4KB)
    __shared__ ull   s_comb[128 * 2 * 4];  // [fl][ff][p] (8KB)
    __shared__ int   s_sel[Bq];
    const int tid = threadIdx.x, blk = blockIdx.x;
    ull* s_hu = (ull*)s_h;

    const int fc = blk % 14;
    const int r3 = blk / 14;
    const int ic = r3 & 7;
    const int m  = (r3 >> 3) & 1;
    const int e  = r3 >> 4;

    if (tid < Bq) s_sel[tid] = g_selG[tid];
    ((float4*)s_h)[tid] = ((const float4*)(g_h2t + ic * 128 * Bq))[tid];
    __syncthreads();

    bool used = false;
#pragma unroll
    for (int b = 0; b < Bq; b++) used |= (s_sel[b] == e);
    if (!used) return;

    const int half = tid >> 7;
    const int fl   = tid & 127;
    const int f    = fc * 256 + fl * 2;
    const int ibl  = half * 64;
    const float* wp = (m ? uw : gw) + (size_t)e * Dq * Fq
                    + (size_t)(ic * 128 + ibl) * Fq + f;

    ull acc[2][4];
#pragma unroll
    for (int ff = 0; ff < 2; ff++)
#pragma unroll
        for (int p = 0; p < 4; p++) acc[ff][p] = 0;

    float2 wa[8], wb[8];
#pragma unroll
    for (int u = 0; u < 8; u++) wa[u] = *(const float2*)(wp + (size_t)u * Fq);
#pragma unroll
    for (int r8 = 0; r8 < 8; r8++) {
        if (r8 < 7) {
#pragma unroll
            for (int u = 0; u < 8; u++)
                wb[u] = *(const float2*)(wp + (size_t)((r8 + 1) * 8 + u) * Fq);
        }
        int il = ibl + r8 * 8;
#pragma unroll
        for (int u = 0; u < 8; u++) {
            ull wx = pack2(wa[u].x, wa[u].x);
            ull wy = pack2(wa[u].y, wa[u].y);
#pragma unroll
            for (int p = 0; p < 4; p++) {
                ull h2 = s_hu[(il + u) * 4 + p];
                FMA2(acc[0][p], h2, wx);
                FMA2(acc[1][p], h2, wy);
            }
        }
#pragma unroll
        for (int u = 0; u < 8; u++) wa[u] = wb[u];
    }

    if (half == 1) {
#pragma unroll
        for (int ff = 0; ff < 2; ff++)
#pragma unroll
            for (int p = 0; p < 4; p++) s_comb[fl * 8 + ff * 4 + p] = acc[ff][p];
    }
    __syncthreads();
    if (half == 0) {
        float* dst = (m ? g_accu : g_accg) + (size_t)e * Bq * Fq + f;
#pragma unroll
        for (int ff = 0; ff < 2; ff++) {
#pragma unroll
            for (int p = 0; p < 4; p++) {
                ADD2(acc[ff][p], s_comb[fl * 8 + ff * 4 + p]);
                float lo, hi; unpack2(acc[ff][p], lo, hi);
                atomicAdd(&dst[(size_t)(2 * p) * Fq + ff], lo);
                atomicAdd(&dst[(size_t)(2 * p + 1) * Fq + ff], hi);
            }
        }
    }
}

// ============ K4: silu/mask + down, float2 + double-buffered. 512 blocks ============
// blk: dc(2 of 512 d) fastest, then fc(128 of 28 f), e. grid = 512.
__global__ void __launch_bounds__(256, 3) k4_down(const float* __restrict__ dw)
{
    __shared__ float s_t[28 * Bq];
    __shared__ int   s_sel[Bq];
    __shared__ float s_tw[Bq];
    const int tid = threadIdx.x, blk = blockIdx.x;
    ull* s_tu = (ull*)s_t;

    if (tid < Bq) { s_sel[tid] = g_selG[tid]; s_tw[tid] = g_twG[tid]; }
    __syncthreads();
    const int dc = blk & 1;
    const int fc = (blk >> 1) & 127;
    const int e  = blk >> 8;
    bool used = false;
#pragma unroll
    for (int b = 0; b < Bq; b++) used |= (s_sel[b] == e);
    if (!used) return;

    const int f0 = fc * 28;
    if (tid < 224) {
        int fl = tid >> 3, b = tid & 7;
        float tv = 0.f;
        if (s_sel[b] == e) {
            int f = f0 + fl;
            float gg = g_accg[((size_t)e * Bq + b) * Fq + f];
            float uu = g_accu[((size_t)e * Bq + b) * Fq + f];
            tv = s_tw[b] * gg * (1.f / (1.f + expf(-gg))) * uu;
        }
        s_t[fl * 8 + b] = tv;
    }
    __syncthreads();

    const int d = dc * 512 + tid * 2;
    const float* dp = dw + ((size_t)e * Fq + f0) * Dq + d;
    ull acc[2][4];
#pragma unroll
    for (int dd = 0; dd < 2; dd++)
#pragma unroll
        for (int p = 0; p < 4; p++) acc[dd][p] = 0;

    float2 wa[4], wb[4];
#pragma unroll
    for (int u = 0; u < 4; u++) wa[u] = *(const float2*)(dp + (size_t)u * Dq);
#pragma unroll
    for (int r4 = 0; r4 < 7; r4++) {
        if (r4 < 6) {
#pragma unroll
            for (int u = 0; u < 4; u++)
                wb[u] = *(const float2*)(dp + (size_t)((r4 + 1) * 4 + u) * Dq);
        }
#pragma unroll
        for (int u = 0; u < 4; u++) {
            ull wx = pack2(wa[u].x, wa[u].x);
            ull wy = pack2(wa[u].y, wa[u].y);
#pragma unroll
            for (int p = 0; p < 4; p++) {
                ull t2 = s_tu[(r4 * 4 + u) * 4 + p];
                FMA2(acc[0][p], t2, wx);
                FMA2(acc[1][p], t2, wy);
            }
        }
#pragma unroll
        for (int u = 0; u < 4; u++) wa[u] = wb[u];
    }
#pragma unroll
    for (int dd = 0; dd < 2; dd++)
#pragma unroll
        for (int p = 0; p < 4; p++) {
            float lo, hi; unpack2(acc[dd][p], lo, hi);
            atomicAdd(&g_y[(2 * p) * Dq + d + dd], lo);
            atomicAdd(&g_y[(2 * p + 1) * Dq + d + dd], hi);
        }
}

// ============ K5: final rmsnorm + score head ============
__global__ void __launch_bounds__(256) k5_final(
    const float* __restrict__ hidden, const float* __restrict__ flnw,
    const float* __restrict__ sw, float* __restrict__ out)
{
    __shared__ float s_red[8 * 8];
    __shared__ float s_out[8];
    __shared__ float s_rs[1];
    const int tid = threadIdx.x, b = blockIdx.x;
    float xr[4];
    float ssv[1]; ssv[0] = 0.f;
#pragma unroll
    for (int it = 0; it < 4; it++) {
        int d = tid + it * 256;
        xr[it] = hidden[(size_t)b * Sq * Dq + d] + g_attn[b * Dq + d] + g_y[b * Dq + d];
        ssv[0] += xr[it] * xr[it];
    }
    breduce<1, 8>(ssv, s_red, s_out);
    if (tid == 0) s_rs[0] = rsqrtf(s_out[0] * (1.f / Dq) + EPSq);
    __syncthreads();
    float rs = s_rs[0];
    float p[2]; p[0] = 0.f; p[1] = 0.f;
#pragma unroll
    for (int it = 0; it < 4; it++) {
        int d = tid + it * 256;
        float xn = xr[it] * rs * flnw[d];
        p[0] = fmaf(xn, sw[d * 2 + 0], p[0]);
        p[1] = fmaf(xn, sw[d * 2 + 1], p[1]);
    }
    breduce<2, 8>(p, s_red, s_out);
    if (tid == 0) {
        out[b * 2 + 0] = s_out[0];
        out[b * 2 + 1] = s_out[1];
    }
}

// ---------------- launch ----------------
extern "C" void kernel_launch(void* const* d_in, const int* in_sizes, int n_in,
                              void* d_out, int out_size) {
    (void)in_sizes; (void)n_in; (void)out_size;
    const float* hidden = (const float*)d_in[0];
    const float* ln1w   = (const float*)d_in[1];
    // d_in[2]=q_w, d_in[3]=k_w: provably unused (causal token-0 softmax == 1)
    const float* vw     = (const float*)d_in[4];
    const float* ow     = (const float*)d_in[5];
    const float* ln2w   = (const float*)d_in[6];
    const float* rw     = (const float*)d_in[7];
    const float* gw     = (const float*)d_in[8];
    const float* uw     = (const float*)d_in[9];
    const float* dw     = (const float*)d_in[10];
    const float* flnw   = (const float*)d_in[11];
    const float* sw     = (const float*)d_in[12];
    float* out = (float*)d_out;

    k0_prep<<<Bq, 256>>>(hidden, ln1w);
    k1_v<<<256, 256>>>(vw);
    k2_o<<<256, 256>>>(ow);
    k2b_h2<<<Bq, 256>>>(hidden, ln2w, rw);
    k3_gateup<<<448, 256>>>(gw, uw);
    k4_down<<<512, 256>>>(dw);
    k5_final<<<Bq, 256>>>(hidden, flnw, sw, out);
}

// round 14
// speedup vs baseline: 1.0544x; 1.0544x over previous
#include <cuda_runtime.h>
#include <math.h>

#define Bq 8
#define Sq 1024
#define Dq 1024
#define Fq 3584
#define Eq 2
#define EPSq 1e-6f

typedef unsigned long long ull;

// ---------------- device scratch (no allocation) ----------------
__device__ ull   g_pvu[64 * 4 * Dq];        // v0 partials [ic*4+p][j] (b-pairs)
__device__ float g_attn[Bq * Dq];           // attn output (atomic)
__device__ float g_h2t[Dq * Bq];            // h2 transposed [d][b]
__device__ ull   g_pgu[32 * 4 * Fq];        // gate/up partials [(e*2+m)*8+ic][p][f]
__device__ float g_y[Bq * Dq];              // moe output (atomic)
__device__ int   g_selG[Bq];                // router selection
__device__ float g_twG[Bq];                 // router top weight

// ---------------- f32x2 helpers ----------------
__device__ __forceinline__ ull pack2(float lo, float hi) {
    ull r;
    asm("mov.b64 %0, {%1, %2};" : "=l"(r) : "r"(__float_as_uint(lo)), "r"(__float_as_uint(hi)));
    return r;
}
__device__ __forceinline__ void unpack2(ull v, float& lo, float& hi) {
    unsigned a, b;
    asm("mov.b64 {%0, %1}, %2;" : "=r"(a), "=r"(b) : "l"(v));
    lo = __uint_as_float(a); hi = __uint_as_float(b);
}
#define FMA2(d, a, b) asm("fma.rn.f32x2 %0, %1, %2, %0;" : "+l"(d) : "l"(a), "l"(b))
#define ADD2(d, a)    asm("add.rn.f32x2 %0, %0, %1;"     : "+l"(d) : "l"(a))

// ---------------- multi-value block reduction ----------
template <int NV, int NWP>
__device__ __forceinline__ void breduce(const float* v, float* s_red, float* s_out) {
    int lane = threadIdx.x & 31, w = threadIdx.x >> 5;
#pragma unroll
    for (int k = 0; k < NV; k++) {
        float x = v[k];
#pragma unroll
        for (int o = 16; o; o >>= 1) x += __shfl_xor_sync(0xffffffffu, x, o);
        if (lane == 0) s_red[k * NWP + w] = x;
    }
    __syncthreads();
    if (threadIdx.x < NV) {
        float s = 0.f;
#pragma unroll
        for (int j = 0; j < NWP; j++) s += s_red[threadIdx.x * NWP + j];
        s_out[threadIdx.x] = s;
    }
    __syncthreads();
}

// ============ K1: zero attn/y + redundant h1 + v0 partials. 256 blocks ============
__global__ void __launch_bounds__(256) k1_prep_v(
    const float* __restrict__ hidden, const float* __restrict__ ln1w,
    const float* __restrict__ vw)
{
    __shared__ float s_ht[Dq * Bq];
    __shared__ float s_red[8 * 8];
    __shared__ float s_out[8];
    __shared__ float s_rs[Bq];
    const int tid = threadIdx.x, blk = blockIdx.x;
    ull* s_htu = (ull*)s_ht;

    for (int idx = blk * 256 + tid; idx < Bq * Dq; idx += 256 * 256) {
        g_attn[idx] = 0.f; g_y[idx] = 0.f;
    }

    float ss[Bq];
#pragma unroll
    for (int b = 0; b < Bq; b++) ss[b] = 0.f;
#pragma unroll
    for (int it = 0; it < 4; it++) {
        int d = tid + it * 256;
#pragma unroll
        for (int b = 0; b < Bq; b++) {
            float v = hidden[(size_t)b * Sq * Dq + d];
            ss[b] += v * v;
        }
    }
    breduce<8, 8>(ss, s_red, s_out);
    if (tid < Bq) s_rs[tid] = rsqrtf(s_out[tid] * (1.f / Dq) + EPSq);
    __syncthreads();
#pragma unroll
    for (int it = 0; it < 4; it++) {
        int d = tid + it * 256;
        float lw = ln1w[d];
#pragma unroll
        for (int b = 0; b < Bq; b++)
            s_ht[d * Bq + b] = hidden[(size_t)b * Sq * Dq + d] * s_rs[b] * lw;
    }
    __syncthreads();

    int ic = blk >> 2, jc = blk & 3;
    int j = jc * 256 + tid, ib = ic * 16;
    float w[16];
#pragma unroll
    for (int u = 0; u < 16; u++) w[u] = vw[(size_t)(ib + u) * Dq + j];
    ull acc[4] = {0, 0, 0, 0};
#pragma unroll
    for (int u = 0; u < 16; u++) {
        ull w2 = pack2(w[u], w[u]);
#pragma unroll
        for (int p = 0; p < 4; p++) FMA2(acc[p], s_htu[(ib + u) * 4 + p], w2);
    }
#pragma unroll
    for (int p = 0; p < 4; p++) g_pvu[(size_t)(ic * 4 + p) * Dq + j] = acc[p];
}

// ============ K2: attn = v0 @ o_w ============
__global__ void __launch_bounds__(256) k2_o(const float* __restrict__ ow)
{
    __shared__ float s_v[16 * Bq];
    const int tid = threadIdx.x, blk = blockIdx.x;
    ull* s_vu = (ull*)s_v;
    int ic = blk >> 2, jc = blk & 3;
    int ib = ic * 16;
    if (tid < 64) {
        int i = tid >> 2, p = tid & 3;
        ull s = 0;
#pragma unroll 8
        for (int c = 0; c < 64; c++) {
            ull v = g_pvu[(size_t)(c * 4 + p) * Dq + ib + i];
            ADD2(s, v);
        }
        s_vu[i * 4 + p] = s;
    }
    __syncthreads();
    int j = jc * 256 + tid;
    float w[16];
#pragma unroll
    for (int u = 0; u < 16; u++) w[u] = ow[(size_t)(ib + u) * Dq + j];
    ull acc[4] = {0, 0, 0, 0};
#pragma unroll
    for (int u = 0; u < 16; u++) {
        ull w2 = pack2(w[u], w[u]);
#pragma unroll
        for (int p = 0; p < 4; p++) FMA2(acc[p], s_vu[u * 4 + p], w2);
    }
#pragma unroll
    for (int p = 0; p < 4; p++) {
        float lo, hi; unpack2(acc[p], lo, hi);
        atomicAdd(&g_attn[(2 * p) * Dq + j], lo);
        atomicAdd(&g_attn[(2 * p + 1) * Dq + j], hi);
    }
}

// ============ K2b: xmid -> h2 (global, transposed) + router. 8 blocks ============
__global__ void __launch_bounds__(256) k2b_h2(
    const float* __restrict__ hidden, const float* __restrict__ ln2w,
    const float* __restrict__ rw)
{
    __shared__ float s_red[2 * 8];
    __shared__ float s_out[2];
    __shared__ float s_rs[1];
    const int tid = threadIdx.x, b = blockIdx.x;
    float xm[4];
    float ss[1]; ss[0] = 0.f;
#pragma unroll
    for (int it = 0; it < 4; it++) {
        int d = tid + it * 256;
        xm[it] = hidden[(size_t)b * Sq * Dq + d] + g_attn[b * Dq + d];
        ss[0] += xm[it] * xm[it];
    }
    breduce<1, 8>(ss, s_red, s_out);
    if (tid == 0) s_rs[0] = rsqrtf(s_out[0] * (1.f / Dq) + EPSq);
    __syncthreads();
    float rs = s_rs[0];
    float l[2]; l[0] = 0.f; l[1] = 0.f;
#pragma unroll
    for (int it = 0; it < 4; it++) {
        int d = tid + it * 256;
        float h2 = xm[it] * rs * ln2w[d];
        g_h2t[d * Bq + b] = h2;
        l[0] = fmaf(h2, rw[d * 2 + 0], l[0]);
        l[1] = fmaf(h2, rw[d * 2 + 1], l[1]);
    }
    breduce<2, 8>(l, s_red, s_out);
    if (tid == 0) {
        float l0 = s_out[0], l1 = s_out[1];
        g_selG[b] = (l1 > l0) ? 1 : 0;
        g_twG[b]  = 1.f / (1.f + expf(-fabsf(l0 - l1)));
    }
}

// ============ K3: gate|up matvec -> partial slots (no atomics). 448 blocks ============
__global__ void __launch_bounds__(256, 3) k3_gateup(
    const float* __restrict__ gw, const float* __restrict__ uw)
{
    __shared__ float s_h[128 * Bq];        // local h2 slice [il][b] (4KB)
    __shared__ ull   s_comb[128 * 2 * 4];  // [fl][ff][p] (8KB)
    __shared__ int   s_sel[Bq];
    const int tid = threadIdx.x, blk = blockIdx.x;
    ull* s_hu = (ull*)s_h;

    const int fc = blk % 14;
    const int r3 = blk / 14;
    const int ic = r3 & 7;
    const int m  = (r3 >> 3) & 1;
    const int e  = r3 >> 4;

    if (tid < Bq) s_sel[tid] = g_selG[tid];
    ((float4*)s_h)[tid] = ((const float4*)(g_h2t + ic * 128 * Bq))[tid];
    __syncthreads();

    bool used = false;
#pragma unroll
    for (int b = 0; b < Bq; b++) used |= (s_sel[b] == e);
    if (!used) return;

    const int half = tid >> 7;
    const int fl   = tid & 127;
    const int f    = fc * 256 + fl * 2;
    const int ibl  = half * 64;
    const float* wp = (m ? uw : gw) + (size_t)e * Dq * Fq
                    + (size_t)(ic * 128 + ibl) * Fq + f;

    ull acc[2][4];
#pragma unroll
    for (int ff = 0; ff < 2; ff++)
#pragma unroll
        for (int p = 0; p < 4; p++) acc[ff][p] = 0;

    float2 wa[8], wb[8];
#pragma unroll
    for (int u = 0; u < 8; u++) wa[u] = *(const float2*)(wp + (size_t)u * Fq);
#pragma unroll
    for (int r8 = 0; r8 < 8; r8++) {
        if (r8 < 7) {
#pragma unroll
            for (int u = 0; u < 8; u++)
                wb[u] = *(const float2*)(wp + (size_t)((r8 + 1) * 8 + u) * Fq);
        }
        int il = ibl + r8 * 8;
#pragma unroll
        for (int u = 0; u < 8; u++) {
            ull wx = pack2(wa[u].x, wa[u].x);
            ull wy = pack2(wa[u].y, wa[u].y);
#pragma unroll
            for (int p = 0; p < 4; p++) {
                ull h2 = s_hu[(il + u) * 4 + p];
                FMA2(acc[0][p], h2, wx);
                FMA2(acc[1][p], h2, wy);
            }
        }
#pragma unroll
        for (int u = 0; u < 8; u++) wa[u] = wb[u];
    }

    if (half == 1) {
#pragma unroll
        for (int ff = 0; ff < 2; ff++)
#pragma unroll
            for (int p = 0; p < 4; p++) s_comb[fl * 8 + ff * 4 + p] = acc[ff][p];
    }
    __syncthreads();
    if (half == 0) {
        // plain stores into partial slot [(e*2+m)*8+ic][p][f]
        ull* dst = g_pgu + (size_t)(((e * 2 + m) * 8 + ic) * 4) * Fq;
#pragma unroll
        for (int ff = 0; ff < 2; ff++) {
#pragma unroll
            for (int p = 0; p < 4; p++) {
                ADD2(acc[ff][p], s_comb[fl * 8 + ff * 4 + p]);
                dst[(size_t)p * Fq + f + ff] = acc[ff][p];
            }
        }
    }
}

// ============ K4: silu/mask (sum partials) + down. 256 blocks ============
// blk: dc(2 of 512 d) fastest, then fc(64 of 56 f), e. grid = 256.
__global__ void __launch_bounds__(256, 3) k4_down(const float* __restrict__ dw)
{
    __shared__ float s_t[56 * Bq];
    __shared__ int   s_sel[Bq];
    __shared__ float s_tw[Bq];
    const int tid = threadIdx.x, blk = blockIdx.x;
    ull* s_tu = (ull*)s_t;

    if (tid < Bq) { s_sel[tid] = g_selG[tid]; s_tw[tid] = g_twG[tid]; }
    __syncthreads();
    const int dc = blk & 1;
    const int fc = (blk >> 1) & 63;
    const int e  = blk >> 7;
    bool used = false;
#pragma unroll
    for (int b = 0; b < Bq; b++) used |= (s_sel[b] == e);
    if (!used) return;

    const int f0 = fc * 56;
    // t-build: 56 fl x 4 b-pairs = 224 items; sum 8 ic partials per (m, p, f)
    if (tid < 224) {
        int fl = tid >> 2, p = tid & 3;
        int f = f0 + fl;
        const ull* pg = g_pgu + (size_t)((e * 2 + 0) * 32 + p) * Fq + f;
        const ull* pu = g_pgu + (size_t)((e * 2 + 1) * 32 + p) * Fq + f;
        ull sg = 0, su = 0;
#pragma unroll
        for (int ic = 0; ic < 8; ic++) {
            ADD2(sg, pg[(size_t)ic * 4 * Fq]);
            ADD2(su, pu[(size_t)ic * 4 * Fq]);
        }
        float g0, g1, u0, u1;
        unpack2(sg, g0, g1);
        unpack2(su, u0, u1);
        int b0 = 2 * p, b1 = 2 * p + 1;
        float t0 = 0.f, t1 = 0.f;
        if (s_sel[b0] == e) t0 = s_tw[b0] * g0 * (1.f / (1.f + expf(-g0))) * u0;
        if (s_sel[b1] == e) t1 = s_tw[b1] * g1 * (1.f / (1.f + expf(-g1))) * u1;
        s_t[fl * 8 + b0] = t0;
        s_t[fl * 8 + b1] = t1;
    }
    __syncthreads();

    const int d = dc * 512 + tid * 2;
    const float* dp = dw + ((size_t)e * Fq + f0) * Dq + d;
    ull acc[2][4];
#pragma unroll
    for (int dd = 0; dd < 2; dd++)
#pragma unroll
        for (int p = 0; p < 4; p++) acc[dd][p] = 0;

    float2 wa[8], wb[8];
#pragma unroll
    for (int u = 0; u < 8; u++) wa[u] = *(const float2*)(dp + (size_t)u * Dq);
#pragma unroll
    for (int r8 = 0; r8 < 7; r8++) {
        if (r8 < 6) {
#pragma unroll
            for (int u = 0; u < 8; u++)
                wb[u] = *(const float2*)(dp + (size_t)((r8 + 1) * 8 + u) * Dq);
        }
#pragma unroll
        for (int u = 0; u < 8; u++) {
            ull wx = pack2(wa[u].x, wa[u].x);
            ull wy = pack2(wa[u].y, wa[u].y);
#pragma unroll
            for (int p = 0; p < 4; p++) {
                ull t2 = s_tu[(r8 * 8 + u) * 4 + p];
                FMA2(acc[0][p], t2, wx);
                FMA2(acc[1][p], t2, wy);
            }
        }
#pragma unroll
        for (int u = 0; u < 8; u++) wa[u] = wb[u];
    }
#pragma unroll
    for (int dd = 0; dd < 2; dd++)
#pragma unroll
        for (int p = 0; p < 4; p++) {
            float lo, hi; unpack2(acc[dd][p], lo, hi);
            atomicAdd(&g_y[(2 * p) * Dq + d + dd], lo);
            atomicAdd(&g_y[(2 * p + 1) * Dq + d + dd], hi);
        }
}

// ============ K5: final rmsnorm + score head ============
__global__ void __launch_bounds__(256) k5_final(
    const float* __restrict__ hidden, const float* __restrict__ flnw,
    const float* __restrict__ sw, float* __restrict__ out)
{
    __shared__ float s_red[8 * 8];
    __shared__ float s_out[8];
    __shared__ float s_rs[1];
    const int tid = threadIdx.x, b = blockIdx.x;
    float xr[4];
    float ssv[1]; ssv[0] = 0.f;
#pragma unroll
    for (int it = 0; it < 4; it++) {
        int d = tid + it * 256;
        xr[it] = hidden[(size_t)b * Sq * Dq + d] + g_attn[b * Dq + d] + g_y[b * Dq + d];
        ssv[0] += xr[it] * xr[it];
    }
    breduce<1, 8>(ssv, s_red, s_out);
    if (tid == 0) s_rs[0] = rsqrtf(s_out[0] * (1.f / Dq) + EPSq);
    __syncthreads();
    float rs = s_rs[0];
    float p[2]; p[0] = 0.f; p[1] = 0.f;
#pragma unroll
    for (int it = 0; it < 4; it++) {
        int d = tid + it * 256;
        float xn = xr[it] * rs * flnw[d];
        p[0] = fmaf(xn, sw[d * 2 + 0], p[0]);
        p[1] = fmaf(xn, sw[d * 2 + 1], p[1]);
    }
    breduce<2, 8>(p, s_red, s_out);
    if (tid == 0) {
        out[b * 2 + 0] = s_out[0];
        out[b * 2 + 1] = s_out[1];
    }
}

// ---------------- launch ----------------
extern "C" void kernel_launch(void* const* d_in, const int* in_sizes, int n_in,
                              void* d_out, int out_size) {
    (void)in_sizes; (void)n_in; (void)out_size;
    const float* hidden = (const float*)d_in[0];
    const float* ln1w   = (const float*)d_in[1];
    // d_in[2]=q_w, d_in[3]=k_w: provably unused (causal token-0 softmax == 1)
    const float* vw     = (const float*)d_in[4];
    const float* ow     = (const float*)d_in[5];
    const float* ln2w   = (const float*)d_in[6];
    const float* rw     = (const float*)d_in[7];
    const float* gw     = (const float*)d_in[8];
    const float* uw     = (const float*)d_in[9];
    const float* dw     = (const float*)d_in[10];
    const float* flnw   = (const float*)d_in[11];
    const float* sw     = (const float*)d_in[12];
    float* out = (float*)d_out;

    k1_prep_v<<<256, 256>>>(hidden, ln1w, vw);
    k2_o<<<256, 256>>>(ow);
    k2b_h2<<<Bq, 256>>>(hidden, ln2w, rw);
    k3_gateup<<<448, 256>>>(gw, uw);
    k4_down<<<256, 256>>>(dw);
    k5_final<<<Bq, 256>>>(hidden, flnw, sw, out);
}

// round 15
// speedup vs baseline: 1.1238x; 1.0658x over previous
#include <cuda_runtime.h>
#include <math.h>

#define Bq 8
#define Sq 1024
#define Dq 1024
#define Fq 3584
#define Eq 2
#define EPSq 1e-6f

typedef unsigned long long ull;

// ---------------- device scratch (no allocation) ----------------
__device__ ull   g_pvu[64 * 4 * Dq];        // v0 partials (unscaled) [ic*4+p][j]
__device__ float g_attn[Bq * Dq];           // attn output (atomic)
__device__ float g_accg[Eq * Bq * Fq];      // gate raw acc (atomic, unscaled by rs2)
__device__ float g_accu[Eq * Bq * Fq];      // up raw acc (atomic, unscaled by rs2)
__device__ float g_y[Bq * Dq];              // moe output (atomic)

// ---------------- f32x2 helpers ----------------
__device__ __forceinline__ ull pack2(float lo, float hi) {
    ull r;
    asm("mov.b64 %0, {%1, %2};" : "=l"(r) : "r"(__float_as_uint(lo)), "r"(__float_as_uint(hi)));
    return r;
}
__device__ __forceinline__ void unpack2(ull v, float& lo, float& hi) {
    unsigned a, b;
    asm("mov.b64 {%0, %1}, %2;" : "=r"(a), "=r"(b) : "l"(v));
    lo = __uint_as_float(a); hi = __uint_as_float(b);
}
#define FMA2(d, a, b) asm("fma.rn.f32x2 %0, %1, %2, %0;" : "+l"(d) : "l"(a), "l"(b))
#define ADD2(d, a)    asm("add.rn.f32x2 %0, %0, %1;"     : "+l"(d) : "l"(a))

// ---------------- multi-value block reduction (8 warps) ----------
template <int NV>
__device__ __forceinline__ void breduce(const float* v, float* s_red, float* s_out) {
    int lane = threadIdx.x & 31, w = threadIdx.x >> 5;
#pragma unroll
    for (int k = 0; k < NV; k++) {
        float x = v[k];
#pragma unroll
        for (int o = 16; o; o >>= 1) x += __shfl_xor_sync(0xffffffffu, x, o);
        if (lane == 0) s_red[k * 8 + w] = x;
    }
    __syncthreads();
    if (threadIdx.x < NV) {
        float s = 0.f;
#pragma unroll
        for (int j = 0; j < 8; j++) s += s_red[threadIdx.x * 8 + j];
        s_out[threadIdx.x] = s;
    }
    __syncthreads();
}

// ============ K1: zero accs + v0 raw partials (no rmsnorm). 256 blocks ============
__global__ void __launch_bounds__(256) k1_v(
    const float* __restrict__ hidden, const float* __restrict__ ln1w,
    const float* __restrict__ vw)
{
    __shared__ float s_h[16 * Bq];   // hm1 slice [u][b] = x*ln1w
    const int tid = threadIdx.x, blk = blockIdx.x;
    ull* s_hu = (ull*)s_h;

    // zero atomic accumulators
    for (int idx = blk * 256 + tid; idx < Eq * Bq * Fq; idx += 256 * 256) {
        g_accg[idx] = 0.f; g_accu[idx] = 0.f;
    }
    for (int idx = blk * 256 + tid; idx < Bq * Dq; idx += 256 * 256) {
        g_attn[idx] = 0.f; g_y[idx] = 0.f;
    }

    const int ic = blk >> 2, jc = blk & 3;
    const int ib = ic * 16;
    if (tid < 128) {
        int u = tid >> 3, b = tid & 7;
        s_h[u * 8 + b] = hidden[(size_t)b * Sq * Dq + ib + u] * ln1w[ib + u];
    }
    __syncthreads();

    int j = jc * 256 + tid;
    float w[16];
#pragma unroll
    for (int u = 0; u < 16; u++) w[u] = vw[(size_t)(ib + u) * Dq + j];
    ull acc[4] = {0, 0, 0, 0};
#pragma unroll
    for (int u = 0; u < 16; u++) {
        ull w2 = pack2(w[u], w[u]);
#pragma unroll
        for (int p = 0; p < 4; p++) FMA2(acc[p], s_hu[u * 4 + p], w2);
    }
#pragma unroll
    for (int p = 0; p < 4; p++) g_pvu[(size_t)(ic * 4 + p) * Dq + j] = acc[p];
}

// ============ K2: rs1 (redundant) + attn = rs1 * v0raw @ o_w. 256 blocks ============
__global__ void __launch_bounds__(256) k2_o(
    const float* __restrict__ hidden, const float* __restrict__ ow)
{
    __shared__ float s_v[16 * Bq];
    __shared__ float s_red[8 * 8];
    __shared__ float s_out[8];
    __shared__ float s_rs[Bq];
    const int tid = threadIdx.x, blk = blockIdx.x;
    ull* s_vu = (ull*)s_v;

    // rs1 per batch (redundant per block; hidden token-0 is L2-hot)
    {
        float ss[Bq];
#pragma unroll
        for (int b = 0; b < Bq; b++) ss[b] = 0.f;
#pragma unroll
        for (int it = 0; it < 4; it++) {
            int d = tid + it * 256;
#pragma unroll
            for (int b = 0; b < Bq; b++) {
                float v = hidden[(size_t)b * Sq * Dq + d];
                ss[b] += v * v;
            }
        }
        breduce<8>(ss, s_red, s_out);
        if (tid < Bq) s_rs[tid] = rsqrtf(s_out[tid] * (1.f / Dq) + EPSq);
        __syncthreads();
    }

    int ic = blk >> 2, jc = blk & 3;
    int ib = ic * 16;
    if (tid < 64) {
        int i = tid >> 2, p = tid & 3;
        ull s = 0;
#pragma unroll 8
        for (int c = 0; c < 64; c++) {
            ull v = g_pvu[(size_t)(c * 4 + p) * Dq + ib + i];
            ADD2(s, v);
        }
        float lo, hi; unpack2(s, lo, hi);
        s_vu[i * 4 + p] = pack2(lo * s_rs[2 * p], hi * s_rs[2 * p + 1]);
    }
    __syncthreads();
    int j = jc * 256 + tid;
    float w[16];
#pragma unroll
    for (int u = 0; u < 16; u++) w[u] = ow[(size_t)(ib + u) * Dq + j];
    ull acc[4] = {0, 0, 0, 0};
#pragma unroll
    for (int u = 0; u < 16; u++) {
        ull w2 = pack2(w[u], w[u]);
#pragma unroll
        for (int p = 0; p < 4; p++) FMA2(acc[p], s_vu[u * 4 + p], w2);
    }
#pragma unroll
    for (int p = 0; p < 4; p++) {
        float lo, hi; unpack2(acc[p], lo, hi);
        atomicAdd(&g_attn[(2 * p) * Dq + j], lo);
        atomicAdd(&g_attn[(2 * p + 1) * Dq + j], hi);
    }
}

// ============ K3: gate|up raw matvec (no rmsnorm, no router). 448 blocks ============
__global__ void __launch_bounds__(256, 3) k3_gateup(
    const float* __restrict__ hidden, const float* __restrict__ ln2w,
    const float* __restrict__ gw, const float* __restrict__ uw)
{
    __shared__ float s_h[128 * Bq];        // hm2 slice [il][b] = (x+attn)*ln2w (4KB)
    __shared__ ull   s_comb[128 * 2 * 4];  // [fl][ff][p] (8KB)
    const int tid = threadIdx.x, blk = blockIdx.x;
    ull* s_hu = (ull*)s_h;

    const int fc = blk % 14;
    const int r3 = blk / 14;
    const int ic = r3 & 7;
    const int m  = (r3 >> 3) & 1;
    const int e  = r3 >> 4;

    // local hm2 slice: rows [ic*128, ic*128+128), all 8 batches (no reduction!)
#pragma unroll
    for (int k = 0; k < 4; k++) {
        int idx = tid + k * 256;
        int il = idx >> 3, b = idx & 7;
        int i = ic * 128 + il;
        s_h[il * 8 + b] = (hidden[(size_t)b * Sq * Dq + i] + g_attn[b * Dq + i]) * ln2w[i];
    }
    __syncthreads();

    const int half = tid >> 7;
    const int fl   = tid & 127;
    const int f    = fc * 256 + fl * 2;
    const int ibl  = half * 64;
    const float* wp = (m ? uw : gw) + (size_t)e * Dq * Fq
                    + (size_t)(ic * 128 + ibl) * Fq + f;

    ull acc[2][4];
#pragma unroll
    for (int ff = 0; ff < 2; ff++)
#pragma unroll
        for (int p = 0; p < 4; p++) acc[ff][p] = 0;

    float2 wa[8], wb[8];
#pragma unroll
    for (int u = 0; u < 8; u++) wa[u] = *(const float2*)(wp + (size_t)u * Fq);
#pragma unroll
    for (int r8 = 0; r8 < 8; r8++) {
        if (r8 < 7) {
#pragma unroll
            for (int u = 0; u < 8; u++)
                wb[u] = *(const float2*)(wp + (size_t)((r8 + 1) * 8 + u) * Fq);
        }
        int il = ibl + r8 * 8;
#pragma unroll
        for (int u = 0; u < 8; u++) {
            ull wx = pack2(wa[u].x, wa[u].x);
            ull wy = pack2(wa[u].y, wa[u].y);
#pragma unroll
            for (int p = 0; p < 4; p++) {
                ull h2 = s_hu[(il + u) * 4 + p];
                FMA2(acc[0][p], h2, wx);
                FMA2(acc[1][p], h2, wy);
            }
        }
#pragma unroll
        for (int u = 0; u < 8; u++) wa[u] = wb[u];
    }

    if (half == 1) {
#pragma unroll
        for (int ff = 0; ff < 2; ff++)
#pragma unroll
            for (int p = 0; p < 4; p++) s_comb[fl * 8 + ff * 4 + p] = acc[ff][p];
    }
    __syncthreads();
    if (half == 0) {
        float* dst = (m ? g_accu : g_accg) + (size_t)e * Bq * Fq + f;
#pragma unroll
        for (int ff = 0; ff < 2; ff++) {
#pragma unroll
            for (int p = 0; p < 4; p++) {
                ADD2(acc[ff][p], s_comb[fl * 8 + ff * 4 + p]);
                float lo, hi; unpack2(acc[ff][p], lo, hi);
                atomicAdd(&dst[(size_t)(2 * p) * Fq + ff], lo);
                atomicAdd(&dst[(size_t)(2 * p + 1) * Fq + ff], hi);
            }
        }
    }
}

// ============ K4: rs2/router (redundant) + silu/mask + down. 256 blocks ============
__global__ void __launch_bounds__(256, 3) k4_down(
    const float* __restrict__ hidden, const float* __restrict__ ln2w,
    const float* __restrict__ rw, const float* __restrict__ dw)
{
    __shared__ float s_t[56 * Bq];
    __shared__ float s_red[24 * 8];
    __shared__ float s_out[24];
    __shared__ float s_rs[Bq];
    __shared__ int   s_sel[Bq];
    __shared__ float s_tw[Bq];
    const int tid = threadIdx.x, blk = blockIdx.x;
    ull* s_tu = (ull*)s_t;

    // fused rs2 + raw router logits, single pass (redundant per block)
    {
        float v[24];
#pragma unroll
        for (int k = 0; k < 24; k++) v[k] = 0.f;
#pragma unroll
        for (int it = 0; it < 4; it++) {
            int d = tid + it * 256;
            float w2d = ln2w[d], r0 = rw[d * 2 + 0], r1 = rw[d * 2 + 1];
#pragma unroll
            for (int b = 0; b < Bq; b++) {
                float xm = hidden[(size_t)b * Sq * Dq + d] + g_attn[b * Dq + d];
                v[b] += xm * xm;
                float hm = xm * w2d;
                v[8 + b]  = fmaf(hm, r0, v[8 + b]);
                v[16 + b] = fmaf(hm, r1, v[16 + b]);
            }
        }
        breduce<24>(v, s_red, s_out);
        if (tid < Bq) {
            float rs2 = rsqrtf(s_out[tid] * (1.f / Dq) + EPSq);
            s_rs[tid] = rs2;
            float l0 = s_out[8 + tid], l1 = s_out[16 + tid];
            s_sel[tid] = (l1 > l0) ? 1 : 0;
            s_tw[tid]  = 1.f / (1.f + expf(-rs2 * fabsf(l0 - l1)));
        }
        __syncthreads();
    }

    const int dc = blk & 1;
    const int fc = (blk >> 1) & 63;
    const int e  = blk >> 7;
    bool used = false;
#pragma unroll
    for (int b = 0; b < Bq; b++) used |= (s_sel[b] == e);
    if (!used) return;

    const int f0 = fc * 56;
    for (int idx = tid; idx < 448; idx += 256) {
        int fl = idx >> 3, b = idx & 7;
        float tv = 0.f;
        if (s_sel[b] == e) {
            int f = f0 + fl;
            float gg = s_rs[b] * g_accg[((size_t)e * Bq + b) * Fq + f];
            float uu = s_rs[b] * g_accu[((size_t)e * Bq + b) * Fq + f];
            tv = s_tw[b] * gg * (1.f / (1.f + expf(-gg))) * uu;
        }
        s_t[fl * 8 + b] = tv;
    }
    __syncthreads();

    const int d = dc * 512 + tid * 2;
    const float* dp = dw + ((size_t)e * Fq + f0) * Dq + d;
    ull acc[2][4];
#pragma unroll
    for (int dd = 0; dd < 2; dd++)
#pragma unroll
        for (int p = 0; p < 4; p++) acc[dd][p] = 0;

    float2 wa[8], wb[8];
#pragma unroll
    for (int u = 0; u < 8; u++) wa[u] = *(const float2*)(dp + (size_t)u * Dq);
#pragma unroll
    for (int r8 = 0; r8 < 7; r8++) {
        if (r8 < 6) {
#pragma unroll
            for (int u = 0; u < 8; u++)
                wb[u] = *(const float2*)(dp + (size_t)((r8 + 1) * 8 + u) * Dq);
        }
#pragma unroll
        for (int u = 0; u < 8; u++) {
            ull wx = pack2(wa[u].x, wa[u].x);
            ull wy = pack2(wa[u].y, wa[u].y);
#pragma unroll
            for (int p = 0; p < 4; p++) {
                ull t2 = s_tu[(r8 * 8 + u) * 4 + p];
                FMA2(acc[0][p], t2, wx);
                FMA2(acc[1][p], t2, wy);
            }
        }
#pragma unroll
        for (int u = 0; u < 8; u++) wa[u] = wb[u];
    }
#pragma unroll
    for (int dd = 0; dd < 2; dd++)
#pragma unroll
        for (int p = 0; p < 4; p++) {
            float lo, hi; unpack2(acc[dd][p], lo, hi);
            atomicAdd(&g_y[(2 * p) * Dq + d + dd], lo);
            atomicAdd(&g_y[(2 * p + 1) * Dq + d + dd], hi);
        }
}

// ============ K5: final rmsnorm + score head. 8 blocks ============
__global__ void __launch_bounds__(256) k5_final(
    const float* __restrict__ hidden, const float* __restrict__ flnw,
    const float* __restrict__ sw, float* __restrict__ out)
{
    __shared__ float s_red[8 * 8];
    __shared__ float s_out[8];
    __shared__ float s_rs[1];
    const int tid = threadIdx.x, b = blockIdx.x;
    float xr[4];
    float ssv[1]; ssv[0] = 0.f;
#pragma unroll
    for (int it = 0; it < 4; it++) {
        int d = tid + it * 256;
        xr[it] = hidden[(size_t)b * Sq * Dq + d] + g_attn[b * Dq + d] + g_y[b * Dq + d];
        ssv[0] += xr[it] * xr[it];
    }
    breduce<1>(ssv, s_red, s_out);
    if (tid == 0) s_rs[0] = rsqrtf(s_out[0] * (1.f / Dq) + EPSq);
    __syncthreads();
    float rs = s_rs[0];
    float p[2]; p[0] = 0.f; p[1] = 0.f;
#pragma unroll
    for (int it = 0; it < 4; it++) {
        int d = tid + it * 256;
        float xn = xr[it] * rs * flnw[d];
        p[0] = fmaf(xn, sw[d * 2 + 0], p[0]);
        p[1] = fmaf(xn, sw[d * 2 + 1], p[1]);
    }
    breduce<2>(p, s_red, s_out);
    if (tid == 0) {
        out[b * 2 + 0] = s_out[0];
        out[b * 2 + 1] = s_out[1];
    }
}

// ---------------- launch ----------------
extern "C" void kernel_launch(void* const* d_in, const int* in_sizes, int n_in,
                              void* d_out, int out_size) {
    (void)in_sizes; (void)n_in; (void)out_size;
    const float* hidden = (const float*)d_in[0];
    const float* ln1w   = (const float*)d_in[1];
    // d_in[2]=q_w, d_in[3]=k_w: provably unused (causal token-0 softmax == 1)
    const float* vw     = (const float*)d_in[4];
    const float* ow     = (const float*)d_in[5];
    const float* ln2w   = (const float*)d_in[6];
    const float* rw     = (const float*)d_in[7];
    const float* gw     = (const float*)d_in[8];
    const float* uw     = (const float*)d_in[9];
    const float* dw     = (const float*)d_in[10];
    const float* flnw   = (const float*)d_in[11];
    const float* sw     = (const float*)d_in[12];
    float* out = (float*)d_out;

    k1_v<<<256, 256>>>(hidden, ln1w, vw);
    k2_o<<<256, 256>>>(hidden, ow);
    k3_gateup<<<448, 256>>>(hidden, ln2w, gw, uw);
    k4_down<<<256, 256>>>(hidden, ln2w, rw, dw);
    k5_final<<<Bq, 256>>>(hidden, flnw, sw, out);
}